// round 14
// baseline (speedup 1.0000x reference)
#include <cuda_runtime.h>
#include <cuda_bf16.h>
#include <cuda_fp16.h>
#include <math_constants.h>
#include <cstdint>

// ---------------------------------------------------------------------------
// MultiHeadAttention, B=2,S=2048,H=16,D=64,E=1024. All-fp16 HMMA pipeline,
// single-pass everywhere.
//   1) qkv(fp16) = x_f16 @ Wattn_f16 + b      [single-pass GEMM, BK=64]
//   2) att(fp16) = flash(qkv)                  [S=Qh*Kh, O=Ph*Vh]
//   3) out(fp32) = att @ Wproj_f16 + b         [single-pass GEMM]
// Round 14: flash softmax vectorized — ex2.approx.f16x2 (halves MUFU, fuses
// the P-packing), row sums via MMA against an all-ones fragment (kills the
// scalar sum + shuffles, makes l exactly consistent with fp16 P).
// ---------------------------------------------------------------------------

#define S_LEN   2048
#define N_EMBD  1024
#define E3      3072
#define N_HEADS 16
#define M_ROWS  4096

__device__ __half g_xf[(size_t)M_ROWS * N_EMBD];
__device__ __half g_attf[(size_t)M_ROWS * N_EMBD];
__device__ __half g_qkv[(size_t)M_ROWS * E3];
__device__ __half g_wa[(size_t)E3 * N_EMBD];     // W_attn^T fp16
__device__ __half g_wp[(size_t)N_EMBD * N_EMBD]; // W_proj^T fp16

// ------------------------- helpers ------------------------------------------
__device__ __forceinline__ uint32_t smem_u32(const void* p) {
    uint32_t a;
    asm("{ .reg .u64 t; cvta.to.shared.u64 t, %1; cvt.u32.u64 %0, t; }"
        : "=r"(a) : "l"(p));
    return a;
}
__device__ __forceinline__ void cp16(uint32_t dst, const void* src) {
    asm volatile("cp.async.cg.shared.global [%0], [%1], 16;" :: "r"(dst), "l"(src));
}
#define CP_COMMIT() asm volatile("cp.async.commit_group;" ::: "memory")
#define CP_WAIT1()  asm volatile("cp.async.wait_group 1;"  ::: "memory")

__device__ __forceinline__ void ldsm4(uint32_t* r, uint32_t addr) {
    asm volatile("ldmatrix.sync.aligned.m8n8.x4.shared.b16 {%0,%1,%2,%3}, [%4];"
                 : "=r"(r[0]), "=r"(r[1]), "=r"(r[2]), "=r"(r[3]) : "r"(addr));
}
__device__ __forceinline__ void ldsm4t(uint32_t* r, uint32_t addr) {
    asm volatile("ldmatrix.sync.aligned.m8n8.x4.trans.shared.b16 {%0,%1,%2,%3}, [%4];"
                 : "=r"(r[0]), "=r"(r[1]), "=r"(r[2]), "=r"(r[3]) : "r"(addr));
}
__device__ __forceinline__ void mma16816h(float* d, const uint32_t* a, const uint32_t* b) {
    asm volatile(
        "mma.sync.aligned.m16n8k16.row.col.f32.f16.f16.f32 "
        "{%0,%1,%2,%3}, {%4,%5,%6,%7}, {%8,%9}, {%0,%1,%2,%3};"
        : "+f"(d[0]), "+f"(d[1]), "+f"(d[2]), "+f"(d[3])
        : "r"(a[0]), "r"(a[1]), "r"(a[2]), "r"(a[3]), "r"(b[0]), "r"(b[1]));
}
__device__ __forceinline__ uint32_t pack2h(float a, float b) {
    uint32_t r;
    asm("cvt.rn.f16x2.f32 %0, %1, %2;" : "=r"(r) : "f"(b), "f"(a));
    return r;
}
// packed fp16x2 exp2
__device__ __forceinline__ uint32_t ex2_h2(uint32_t h2) {
    asm("ex2.approx.f16x2 %0, %0;" : "+r"(h2));
    return h2;
}

// ---------------------------------------------------------------------------
__global__ void cvt_f16(const float* __restrict__ in, __half* __restrict__ out, int n4)
{
    int i = blockIdx.x * blockDim.x + threadIdx.x;
    if (i >= n4) return;
    float4 v = ((const float4*)in)[i];
    uint2 o = { pack2h(v.x, v.y), pack2h(v.z, v.w) };
    ((uint2*)out)[i] = o;
}

// transpose W[K][N] -> T[N][K], fp16
__global__ void cvt_t_16(const float* __restrict__ W, __half* __restrict__ T, int K, int N)
{
    __shared__ float tile[32][33];
    int k0 = blockIdx.y * 32, n0 = blockIdx.x * 32;
    int tx = threadIdx.x, ty = threadIdx.y;
#pragma unroll
    for (int i = ty; i < 32; i += 8)
        tile[i][tx] = W[(size_t)(k0 + i) * N + n0 + tx];
    __syncthreads();
#pragma unroll
    for (int i = ty; i < 32; i += 8)
        T[(size_t)(n0 + i) * K + k0 + tx] = __float2half_rn(tile[tx][i]);
}

// ---------------------------------------------------------------------------
// fp16 single-pass GEMM (unchanged from round 13).
// ---------------------------------------------------------------------------
#define GMATB  16384
#define STAGEB (2 * GMATB)
#define GSMEM  (3 * STAGEB)      // 98304

template <bool F16OUT>
__global__ __launch_bounds__(128, 2)
void gemm_mma(const __half* __restrict__ A, const __half* __restrict__ B,
              const float* __restrict__ bias, float* __restrict__ Cf,
              __half* __restrict__ Ch, int M, int N, int K)
{
    extern __shared__ char smem[];
    uint32_t sb = smem_u32(smem);
    int t = threadIdx.x, wid = t >> 5, lid = t & 31;
    int m0 = blockIdx.y * 128, n0 = blockIdx.x * 128;
    int wm = wid & 1, wn = wid >> 1;

    const __half* gp[2] = { A + (size_t)m0 * K, B + (size_t)n0 * K };

    const int lc = t & 7;
    const int lr = t >> 3;
    const uint32_t wbase = (uint32_t)((lc ^ (lr & 7)) << 4) + lr * 128;

    float acc[4][8][4];
#pragma unroll
    for (int i = 0; i < 4; i++)
#pragma unroll
        for (int j = 0; j < 8; j++)
#pragma unroll
            for (int v = 0; v < 4; v++) acc[i][j][v] = 0.f;

    int nkt = K / 64;

#pragma unroll
    for (int s = 0; s < 2; s++) {
        uint32_t st = sb + s * STAGEB;
        int koff = s * 64;
#pragma unroll
        for (int mat = 0; mat < 2; mat++)
#pragma unroll
            for (int r8 = 0; r8 < 8; r8++)
                cp16(st + mat * GMATB + wbase + r8 * 16 * 128,
                     gp[mat] + (size_t)(lr + r8 * 16) * K + koff + lc * 8);
        CP_COMMIT();
    }

    const int arow = lid & 15, asel = lid >> 4;
    const int axor = arow & 7;
    const int browl = ((lid >> 4) & 1) * 8 + (lid & 7);
    const int bsel = (lid >> 3) & 1;
    const int bxor = browl & 7;

    int rd = 0, wr = 2;
    for (int kt = 0; kt < nkt; kt++) {
        CP_WAIT1();
        __syncthreads();

        uint32_t st = sb + rd * STAGEB;
        uint32_t aRow = st + (uint32_t)(wm * 64) * 128;
        uint32_t bRow = st + GMATB + (uint32_t)(wn * 64) * 128;

#pragma unroll
        for (int kb = 0; kb < 4; kb++) {
            uint32_t ah[4][4];
#pragma unroll
            for (int mt = 0; mt < 4; mt++)
                ldsm4(ah[mt], aRow + (uint32_t)(mt * 16 + arow) * 128
                              + (uint32_t)(((kb * 2 + asel) ^ axor) << 4));
#pragma unroll
            for (int p = 0; p < 4; p++) {
                uint32_t bh[4];
                ldsm4(bh, bRow + (uint32_t)(p * 16 + browl) * 128
                          + (uint32_t)(((kb * 2 + bsel) ^ bxor) << 4));
#pragma unroll
                for (int mt = 0; mt < 4; mt++) {
                    mma16816h(acc[mt][2 * p],     ah[mt], &bh[0]);
                    mma16816h(acc[mt][2 * p + 1], ah[mt], &bh[2]);
                }
            }
        }

        if (kt + 2 < nkt) {
            uint32_t st2 = sb + wr * STAGEB;
            int koff = (kt + 2) * 64;
#pragma unroll
            for (int mat = 0; mat < 2; mat++)
#pragma unroll
                for (int r8 = 0; r8 < 8; r8++)
                    cp16(st2 + mat * GMATB + wbase + r8 * 16 * 128,
                         gp[mat] + (size_t)(lr + r8 * 16) * K + koff + lc * 8);
        }
        CP_COMMIT();
        rd = (rd == 2) ? 0 : rd + 1;
        wr = (wr == 2) ? 0 : wr + 1;
    }

    int rA = m0 + wm * 64 + (lid >> 2);
    int cA = n0 + wn * 64 + 2 * (lid & 3);
#pragma unroll
    for (int mt = 0; mt < 4; mt++) {
        int r = rA + mt * 16;
#pragma unroll
        for (int nt = 0; nt < 8; nt++) {
            int c = cA + nt * 8;
            float b0 = bias[c], b1 = bias[c + 1];
            float v00 = acc[mt][nt][0] + b0, v01 = acc[mt][nt][1] + b1;
            float v10 = acc[mt][nt][2] + b0, v11 = acc[mt][nt][3] + b1;
            if (F16OUT) {
                *(uint32_t*)(Ch + (size_t)r * N + c)       = pack2h(v00, v01);
                *(uint32_t*)(Ch + (size_t)(r + 8) * N + c) = pack2h(v10, v11);
            } else {
                float2 w0 = {v00, v01}, w1 = {v10, v11};
                *(float2*)(Cf + (size_t)r * N + c)       = w0;
                *(float2*)(Cf + (size_t)(r + 8) * N + c) = w1;
            }
        }
    }
}

// ---------------------------------------------------------------------------
// fp16 single-pass causal flash attention with vectorized softmax.
// S = Qh*Kh, O = Ph*Vh; P via ex2.f16x2; row sums via MMA vs all-ones.
// ---------------------------------------------------------------------------
#define QMATB   16384
#define FMATB   8192
#define FSTAGE  (2 * FMATB)
#define FSMEM   (QMATB + 2 * FSTAGE)  // 49152
#define SCALE_L2E 0.18033688011112042f

__global__ __launch_bounds__(256, 2)
void flash_mma(const __half* __restrict__ qkv, __half* __restrict__ attf)
{
    extern __shared__ char smem[];
    uint32_t sb = smem_u32(smem);
    int t = threadIdx.x, wid = t >> 5, lid = t & 31;
    int bh = blockIdx.x;
    int b = bh >> 4, hh = bh & 15;
    int qt = (int)gridDim.y - 1 - blockIdx.y;
    int qbase = qt * 128;
    int tok0 = b * S_LEN;

    const uint32_t QH = sb;
    const uint32_t KV0 = sb + QMATB;

    const int qlrow  = t >> 1;
    const int qlcol0 = (t & 1) * 4;
    const int klrow  = t >> 2;
    const int klcol0 = (t & 3) * 2;
    const int klx = klrow & 7;

    {
        size_t rq = (size_t)(tok0 + qbase + qlrow) * E3 + hh * 64;
        int qx = qlrow & 7;
#pragma unroll
        for (int u = 0; u < 4; u++) {
            int ch = qlcol0 + u;
            cp16(QH + qlrow * 128 + ((ch ^ qx) << 4), qkv + rq + ch * 8);
        }
        size_t rk = (size_t)(tok0 + klrow) * E3 + 1024 + hh * 64;
#pragma unroll
        for (int u = 0; u < 2; u++) {
            int ch = klcol0 + u;
            uint32_t d = klrow * 128 + ((ch ^ klx) << 4);
            cp16(KV0 + d,         qkv + rk + ch * 8);
            cp16(KV0 + FMATB + d, qkv + rk + 1024 + ch * 8);
        }
    }
    CP_COMMIT();

    const int arow = lid & 15, asel = lid >> 4;
    const int qrow = wid * 16 + arow;
    const int qx = qrow & 7;
    const int browf = ((lid >> 4) & 1) * 8 + (lid & 7);
    const int bsel = (lid >> 3) & 1;
    const int vrowf = ((lid >> 3) & 1) * 8 + (lid & 7);
    const int vsel = (lid >> 4) & 1;

    uint32_t qh[4][4];
    float o[8][4];
#pragma unroll
    for (int n = 0; n < 8; n++)
#pragma unroll
        for (int v = 0; v < 4; v++) o[n][v] = 0.f;
    float m_lo = -CUDART_INF_F, m_hi = -CUDART_INF_F, l_lo = 0.f, l_hi = 0.f;

    const int rlo = lid >> 2;
    const int rloc = 16 * (wid & 3) + rlo;
    const int mycol0 = 2 * (lid & 3);
    const int kt_d = 2 * qt + (wid >> 2);
    const int ntiles = 2 * qt + 2;
    const uint32_t bones[2] = { 0x3C003C00u, 0x3C003C00u };  // fp16 ones

    for (int kt = 0; kt < ntiles; kt++) {
        if (kt + 1 < ntiles) {
            uint32_t st = KV0 + ((kt + 1) & 1) * FSTAGE;
            size_t rk = (size_t)(tok0 + (kt + 1) * 64 + klrow) * E3 + 1024 + hh * 64;
#pragma unroll
            for (int u = 0; u < 2; u++) {
                int ch = klcol0 + u;
                uint32_t d = klrow * 128 + ((ch ^ klx) << 4);
                cp16(st + d,         qkv + rk + ch * 8);
                cp16(st + FMATB + d, qkv + rk + 1024 + ch * 8);
            }
        }
        CP_COMMIT();
        CP_WAIT1();
        __syncthreads();

        if (kt == 0) {
#pragma unroll
            for (int ks = 0; ks < 4; ks++)
                ldsm4(qh[ks], QH + qrow * 128 + (((ks * 2 + asel) ^ qx) << 4));
        }

        if (kt <= kt_d) {
            uint32_t st = KV0 + (kt & 1) * FSTAGE;

            // ---- S = Qh * Kh ----
            float s[8][4];
#pragma unroll
            for (int n = 0; n < 8; n++)
#pragma unroll
                for (int v = 0; v < 4; v++) s[n][v] = 0.f;

#pragma unroll
            for (int ks = 0; ks < 4; ks++) {
#pragma unroll
                for (int pp = 0; pp < 2; pp++) {
                    int p0 = pp * 2;
                    int rk0 = p0 * 16 + browf, rk1 = rk0 + 16;
                    uint32_t ka0 = st + rk0 * 128 + (((ks * 2 + bsel) ^ (rk0 & 7)) << 4);
                    uint32_t ka1 = st + rk1 * 128 + (((ks * 2 + bsel) ^ (rk1 & 7)) << 4);
                    uint32_t kh0[4], kh1[4];
                    ldsm4(kh0, ka0);
                    ldsm4(kh1, ka1);
                    mma16816h(s[2 * p0],     qh[ks], &kh0[0]);
                    mma16816h(s[2 * p0 + 1], qh[ks], &kh0[2]);
                    mma16816h(s[2 * p0 + 2], qh[ks], &kh1[0]);
                    mma16816h(s[2 * p0 + 3], qh[ks], &kh1[2]);
                }
            }

#pragma unroll
            for (int n = 0; n < 8; n++)
#pragma unroll
                for (int v = 0; v < 4; v++) s[n][v] *= SCALE_L2E;

            if (kt == kt_d) {
#pragma unroll
                for (int n = 0; n < 8; n++) {
                    int c0 = n * 8 + mycol0;
                    if (c0 > rloc)     s[n][0] = -CUDART_INF_F;
                    if (c0 + 1 > rloc) s[n][1] = -CUDART_INF_F;
                    if (c0 > rloc + 8)     s[n][2] = -CUDART_INF_F;
                    if (c0 + 1 > rloc + 8) s[n][3] = -CUDART_INF_F;
                }
            }

            // ---- row max (fp32) ----
            float mt_lo = -CUDART_INF_F, mt_hi = -CUDART_INF_F;
#pragma unroll
            for (int n = 0; n < 8; n++) {
                mt_lo = fmaxf(mt_lo, fmaxf(s[n][0], s[n][1]));
                mt_hi = fmaxf(mt_hi, fmaxf(s[n][2], s[n][3]));
            }
            mt_lo = fmaxf(mt_lo, __shfl_xor_sync(0xffffffffu, mt_lo, 1));
            mt_lo = fmaxf(mt_lo, __shfl_xor_sync(0xffffffffu, mt_lo, 2));
            mt_hi = fmaxf(mt_hi, __shfl_xor_sync(0xffffffffu, mt_hi, 1));
            mt_hi = fmaxf(mt_hi, __shfl_xor_sync(0xffffffffu, mt_hi, 2));

            float mn_lo = fmaxf(m_lo, mt_lo), mn_hi = fmaxf(m_hi, mt_hi);
            float a_lo = exp2f(m_lo - mn_lo), a_hi = exp2f(m_hi - mn_hi);
            m_lo = mn_lo; m_hi = mn_hi;

            // ---- P = exp2(s - m) in packed fp16 (ex2.f16x2) ----
            uint32_t plo[8], phi[8];
#pragma unroll
            for (int n = 0; n < 8; n++) {
                plo[n] = ex2_h2(pack2h(s[n][0] - mn_lo, s[n][1] - mn_lo));
                phi[n] = ex2_h2(pack2h(s[n][2] - mn_hi, s[n][3] - mn_hi));
            }

            // ---- row sums via MMA against all-ones B ----
            float accl[4] = {0.f, 0.f, 0.f, 0.f};
#pragma unroll
            for (int ks = 0; ks < 4; ks++) {
                uint32_t pa[4] = { plo[2 * ks], phi[2 * ks],
                                   plo[2 * ks + 1], phi[2 * ks + 1] };
                mma16816h(accl, pa, bones);
            }
            l_lo = a_lo * l_lo + accl[0];
            l_hi = a_hi * l_hi + accl[2];
#pragma unroll
            for (int n = 0; n < 8; n++) {
                o[n][0] *= a_lo; o[n][1] *= a_lo;
                o[n][2] *= a_hi; o[n][3] *= a_hi;
            }

            // ---- O += Ph * Vh ----
            uint32_t vbase = st + FMATB;
#pragma unroll
            for (int ks = 0; ks < 4; ks++) {
                uint32_t pa[4] = { plo[2 * ks], phi[2 * ks],
                                   plo[2 * ks + 1], phi[2 * ks + 1] };
                int rv = ks * 16 + vrowf;
                int vx = rv & 7;
#pragma unroll
                for (int pp = 0; pp < 2; pp++) {
                    int p0 = pp * 2;
                    uint32_t va0 = vbase + rv * 128 + (((p0 * 2 + vsel) ^ vx) << 4);
                    uint32_t va1 = vbase + rv * 128 + ((((p0 + 1) * 2 + vsel) ^ vx) << 4);
                    uint32_t vh0[4], vh1[4];
                    ldsm4t(vh0, va0);
                    ldsm4t(vh1, va1);
                    mma16816h(o[2 * p0],     pa, &vh0[0]);
                    mma16816h(o[2 * p0 + 1], pa, &vh0[2]);
                    mma16816h(o[2 * p0 + 2], pa, &vh1[0]);
                    mma16816h(o[2 * p0 + 3], pa, &vh1[2]);
                }
            }
        }
        __syncthreads();
    }

    // ---- epilogue: normalize, cast to fp16 ----
    float inv_lo = 1.f / l_lo, inv_hi = 1.f / l_hi;
    int tok_lo = tok0 + qbase + wid * 16 + rlo;
    int tok_hi = tok_lo + 8;
#pragma unroll
    for (int n = 0; n < 8; n++) {
        int c = hh * 64 + n * 8 + mycol0;
        *(uint32_t*)(attf + (size_t)tok_lo * N_EMBD + c) =
            pack2h(o[n][0] * inv_lo, o[n][1] * inv_lo);
        *(uint32_t*)(attf + (size_t)tok_hi * N_EMBD + c) =
            pack2h(o[n][2] * inv_hi, o[n][3] * inv_hi);
    }
}

// ---------------------------------------------------------------------------
extern "C" void kernel_launch(void* const* d_in, const int* in_sizes, int n_in,
                              void* d_out, int out_size)
{
    const float* x      = (const float*)d_in[0];
    const float* W_attn = (const float*)d_in[1];
    const float* b_attn = (const float*)d_in[2];
    const float* W_proj = (const float*)d_in[3];
    const float* b_proj = (const float*)d_in[4];
    float* out = (float*)d_out;

    __half *xf, *attf, *qkv, *wa, *wp;
    cudaGetSymbolAddress((void**)&xf, g_xf);
    cudaGetSymbolAddress((void**)&attf, g_attf);
    cudaGetSymbolAddress((void**)&qkv, g_qkv);
    cudaGetSymbolAddress((void**)&wa, g_wa);
    cudaGetSymbolAddress((void**)&wp, g_wp);

    cudaFuncSetAttribute(gemm_mma<true>,
                         cudaFuncAttributeMaxDynamicSharedMemorySize, GSMEM);
    cudaFuncSetAttribute(gemm_mma<false>,
                         cudaFuncAttributeMaxDynamicSharedMemorySize, GSMEM);
    cudaFuncSetAttribute(flash_mma,
                         cudaFuncAttributeMaxDynamicSharedMemorySize, FSMEM);

    cvt_f16<<<(M_ROWS * N_EMBD / 4 + 255) / 256, 256>>>(x, xf, M_ROWS * N_EMBD / 4);
    cvt_t_16<<<dim3(E3 / 32, N_EMBD / 32), dim3(32, 8)>>>(W_attn, wa, N_EMBD, E3);
    cvt_t_16<<<dim3(N_EMBD / 32, N_EMBD / 32), dim3(32, 8)>>>(W_proj, wp, N_EMBD, N_EMBD);

    gemm_mma<true><<<dim3(E3 / 128, M_ROWS / 128), 128, GSMEM>>>(
        xf, wa, b_attn, nullptr, qkv, M_ROWS, E3, N_EMBD);

    flash_mma<<<dim3(2 * N_HEADS, S_LEN / 128), 256, FSMEM>>>(qkv, attf);

    gemm_mma<false><<<dim3(N_EMBD / 128, M_ROWS / 128), 128, GSMEM>>>(
        attf, wp, b_proj, out, nullptr, M_ROWS, N_EMBD, N_EMBD);
}

// round 15
// speedup vs baseline: 1.0338x; 1.0338x over previous
#include <cuda_runtime.h>
#include <cuda_bf16.h>
#include <cuda_fp16.h>
#include <math_constants.h>
#include <cstdint>

// ---------------------------------------------------------------------------
// MultiHeadAttention, B=2,S=2048,H=16,D=64,E=1024. All-fp16 HMMA pipeline,
// single-pass everywhere.
//   1) qkv(fp16) = x_f16 @ Wattn_f16 + b   [gemm_qkv: 128x96 tiles, BK=32,
//      warp 64x48, 3 CTAs/SM — round-15 wave-packing + occupancy change]
//   2) att(fp16) = flash(qkv)              [S=Qh*Kh, O=Ph*Vh, f16x2 softmax]
//   3) out(fp32) = att @ Wproj_f16 + b     [gemm_mma 128x128, 2 CTAs/SM]
// ---------------------------------------------------------------------------

#define S_LEN   2048
#define N_EMBD  1024
#define E3      3072
#define N_HEADS 16
#define M_ROWS  4096

__device__ __half g_xf[(size_t)M_ROWS * N_EMBD];
__device__ __half g_attf[(size_t)M_ROWS * N_EMBD];
__device__ __half g_qkv[(size_t)M_ROWS * E3];
__device__ __half g_wa[(size_t)E3 * N_EMBD];     // W_attn^T fp16
__device__ __half g_wp[(size_t)N_EMBD * N_EMBD]; // W_proj^T fp16

// ------------------------- helpers ------------------------------------------
__device__ __forceinline__ uint32_t smem_u32(const void* p) {
    uint32_t a;
    asm("{ .reg .u64 t; cvta.to.shared.u64 t, %1; cvt.u32.u64 %0, t; }"
        : "=r"(a) : "l"(p));
    return a;
}
__device__ __forceinline__ void cp16(uint32_t dst, const void* src) {
    asm volatile("cp.async.cg.shared.global [%0], [%1], 16;" :: "r"(dst), "l"(src));
}
#define CP_COMMIT() asm volatile("cp.async.commit_group;" ::: "memory")
#define CP_WAIT1()  asm volatile("cp.async.wait_group 1;"  ::: "memory")

__device__ __forceinline__ void ldsm4(uint32_t* r, uint32_t addr) {
    asm volatile("ldmatrix.sync.aligned.m8n8.x4.shared.b16 {%0,%1,%2,%3}, [%4];"
                 : "=r"(r[0]), "=r"(r[1]), "=r"(r[2]), "=r"(r[3]) : "r"(addr));
}
__device__ __forceinline__ void ldsm4t(uint32_t* r, uint32_t addr) {
    asm volatile("ldmatrix.sync.aligned.m8n8.x4.trans.shared.b16 {%0,%1,%2,%3}, [%4];"
                 : "=r"(r[0]), "=r"(r[1]), "=r"(r[2]), "=r"(r[3]) : "r"(addr));
}
__device__ __forceinline__ void mma16816h(float* d, const uint32_t* a, const uint32_t* b) {
    asm volatile(
        "mma.sync.aligned.m16n8k16.row.col.f32.f16.f16.f32 "
        "{%0,%1,%2,%3}, {%4,%5,%6,%7}, {%8,%9}, {%0,%1,%2,%3};"
        : "+f"(d[0]), "+f"(d[1]), "+f"(d[2]), "+f"(d[3])
        : "r"(a[0]), "r"(a[1]), "r"(a[2]), "r"(a[3]), "r"(b[0]), "r"(b[1]));
}
__device__ __forceinline__ uint32_t pack2h(float a, float b) {
    uint32_t r;
    asm("cvt.rn.f16x2.f32 %0, %1, %2;" : "=r"(r) : "f"(b), "f"(a));
    return r;
}
__device__ __forceinline__ uint32_t ex2_h2(uint32_t h2) {
    asm("ex2.approx.f16x2 %0, %0;" : "+r"(h2));
    return h2;
}

// ---------------------------------------------------------------------------
__global__ void cvt_f16(const float* __restrict__ in, __half* __restrict__ out, int n4)
{
    int i = blockIdx.x * blockDim.x + threadIdx.x;
    if (i >= n4) return;
    float4 v = ((const float4*)in)[i];
    uint2 o = { pack2h(v.x, v.y), pack2h(v.z, v.w) };
    ((uint2*)out)[i] = o;
}

// transpose W[K][N] -> T[N][K], fp16
__global__ void cvt_t_16(const float* __restrict__ W, __half* __restrict__ T, int K, int N)
{
    __shared__ float tile[32][33];
    int k0 = blockIdx.y * 32, n0 = blockIdx.x * 32;
    int tx = threadIdx.x, ty = threadIdx.y;
#pragma unroll
    for (int i = ty; i < 32; i += 8)
        tile[i][tx] = W[(size_t)(k0 + i) * N + n0 + tx];
    __syncthreads();
#pragma unroll
    for (int i = ty; i < 32; i += 8)
        T[(size_t)(n0 + i) * K + k0 + tx] = __float2half_rn(tile[tx][i]);
}

// ---------------------------------------------------------------------------
// QKV GEMM: C[M,N] = A[M,K] @ B[N,K]^T + bias, fp16 out.
// 128x96 CTA tile, BK=32 (64B rows, 4-chunk XOR swizzle), 4 warps (64x48),
// 3 stages x 14KB, 1 barrier/ktile, 3 CTAs/SM, 128 threads.
// ---------------------------------------------------------------------------
#define QAMATB 8192              // A: 128 rows * 64B
#define QBMATB 6144              // B:  96 rows * 64B
#define QSTAGE (QAMATB + QBMATB) // 14336
#define QSMEM  (3 * QSTAGE)      // 43008

__global__ __launch_bounds__(128, 3)
void gemm_qkv(const __half* __restrict__ A, const __half* __restrict__ B,
              const float* __restrict__ bias, __half* __restrict__ C,
              int M, int N, int K)
{
    extern __shared__ char smem[];
    uint32_t sb = smem_u32(smem);
    int t = threadIdx.x, wid = t >> 5, lid = t & 31;
    int m0 = blockIdx.y * 128, n0 = blockIdx.x * 96;
    int wm = wid & 1, wn = wid >> 1;   // 2x2 warps, 64x48 tiles

    const __half* gA = A + (size_t)m0 * K;
    const __half* gB = B + (size_t)n0 * K;

    // loader: chunk lc (16B of 4) in 64B row, base row lr; xor inv. under +32
    const int lc = t & 3;
    const int lr = t >> 2;                    // 0..31
    const uint32_t wofs = (uint32_t)((lc ^ ((lr >> 1) & 3)) << 4) + lr * 64;

    float acc[4][6][4];   // 96 regs
#pragma unroll
    for (int i = 0; i < 4; i++)
#pragma unroll
        for (int j = 0; j < 6; j++)
#pragma unroll
            for (int v = 0; v < 4; v++) acc[i][j][v] = 0.f;

    int nkt = K / 32;   // 32

    // prologue: stages 0,1
#pragma unroll
    for (int s = 0; s < 2; s++) {
        uint32_t st = sb + s * QSTAGE;
        int koff = s * 32;
#pragma unroll
        for (int k4 = 0; k4 < 4; k4++)
            cp16(st + wofs + k4 * 32 * 64,
                 gA + (size_t)(lr + k4 * 32) * K + koff + lc * 8);
#pragma unroll
        for (int k3 = 0; k3 < 3; k3++)
            cp16(st + QAMATB + wofs + k3 * 32 * 64,
                 gB + (size_t)(lr + k3 * 32) * K + koff + lc * 8);
        CP_COMMIT();
    }

    const int arow = lid & 15, asel = lid >> 4;
    const int axor = (arow >> 1) & 3;
    const int browl = ((lid >> 4) & 1) * 8 + (lid & 7);
    const int bsel = (lid >> 3) & 1;
    const int bxor = (browl >> 1) & 3;

    int rd = 0, wr = 2;
    for (int kt = 0; kt < nkt; kt++) {
        CP_WAIT1();
        __syncthreads();

        uint32_t st = sb + rd * QSTAGE;

#pragma unroll
        for (int kb = 0; kb < 2; kb++) {
            uint32_t ah[4][4];
#pragma unroll
            for (int mt = 0; mt < 4; mt++)
                ldsm4(ah[mt], st + (uint32_t)(wm * 64 + mt * 16 + arow) * 64
                              + (uint32_t)(((kb * 2 + asel) ^ axor) << 4));
#pragma unroll
            for (int p = 0; p < 3; p++) {
                uint32_t bh[4];
                ldsm4(bh, st + QAMATB
                          + (uint32_t)(wn * 48 + p * 16 + browl) * 64
                          + (uint32_t)(((kb * 2 + bsel) ^ bxor) << 4));
#pragma unroll
                for (int mt = 0; mt < 4; mt++) {
                    mma16816h(acc[mt][2 * p],     ah[mt], &bh[0]);
                    mma16816h(acc[mt][2 * p + 1], ah[mt], &bh[2]);
                }
            }
        }

        // issue loads for ktile kt+2 (stage wr == (kt-1)%3, drained by this
        // iteration's barrier)
        if (kt + 2 < nkt) {
            uint32_t st2 = sb + wr * QSTAGE;
            int koff = (kt + 2) * 32;
#pragma unroll
            for (int k4 = 0; k4 < 4; k4++)
                cp16(st2 + wofs + k4 * 32 * 64,
                     gA + (size_t)(lr + k4 * 32) * K + koff + lc * 8);
#pragma unroll
            for (int k3 = 0; k3 < 3; k3++)
                cp16(st2 + QAMATB + wofs + k3 * 32 * 64,
                     gB + (size_t)(lr + k3 * 32) * K + koff + lc * 8);
        }
        CP_COMMIT();
        rd = (rd == 2) ? 0 : rd + 1;
        wr = (wr == 2) ? 0 : wr + 1;
    }

    int rA = m0 + wm * 64 + (lid >> 2);
    int cA = n0 + wn * 48 + 2 * (lid & 3);
#pragma unroll
    for (int mt = 0; mt < 4; mt++) {
        int r = rA + mt * 16;
#pragma unroll
        for (int nt = 0; nt < 6; nt++) {
            int c = cA + nt * 8;
            float b0 = bias[c], b1 = bias[c + 1];
            *(uint32_t*)(C + (size_t)r * N + c) =
                pack2h(acc[mt][nt][0] + b0, acc[mt][nt][1] + b1);
            *(uint32_t*)(C + (size_t)(r + 8) * N + c) =
                pack2h(acc[mt][nt][2] + b0, acc[mt][nt][3] + b1);
        }
    }
}

// ---------------------------------------------------------------------------
// Proj GEMM (unchanged round-13 kernel, fp32 out): 128x128, BK=64, 2 CTAs/SM.
// ---------------------------------------------------------------------------
#define GMATB  16384
#define STAGEB (2 * GMATB)
#define GSMEM  (3 * STAGEB)      // 98304

__global__ __launch_bounds__(128, 2)
void gemm_proj(const __half* __restrict__ A, const __half* __restrict__ B,
               const float* __restrict__ bias, float* __restrict__ Cf,
               int M, int N, int K)
{
    extern __shared__ char smem[];
    uint32_t sb = smem_u32(smem);
    int t = threadIdx.x, wid = t >> 5, lid = t & 31;
    int m0 = blockIdx.y * 128, n0 = blockIdx.x * 128;
    int wm = wid & 1, wn = wid >> 1;

    const __half* gp[2] = { A + (size_t)m0 * K, B + (size_t)n0 * K };

    const int lc = t & 7;
    const int lr = t >> 3;
    const uint32_t wbase = (uint32_t)((lc ^ (lr & 7)) << 4) + lr * 128;

    float acc[4][8][4];
#pragma unroll
    for (int i = 0; i < 4; i++)
#pragma unroll
        for (int j = 0; j < 8; j++)
#pragma unroll
            for (int v = 0; v < 4; v++) acc[i][j][v] = 0.f;

    int nkt = K / 64;

#pragma unroll
    for (int s = 0; s < 2; s++) {
        uint32_t st = sb + s * STAGEB;
        int koff = s * 64;
#pragma unroll
        for (int mat = 0; mat < 2; mat++)
#pragma unroll
            for (int r8 = 0; r8 < 8; r8++)
                cp16(st + mat * GMATB + wbase + r8 * 16 * 128,
                     gp[mat] + (size_t)(lr + r8 * 16) * K + koff + lc * 8);
        CP_COMMIT();
    }

    const int arow = lid & 15, asel = lid >> 4;
    const int axor = arow & 7;
    const int browl = ((lid >> 4) & 1) * 8 + (lid & 7);
    const int bsel = (lid >> 3) & 1;
    const int bxor = browl & 7;

    int rd = 0, wr = 2;
    for (int kt = 0; kt < nkt; kt++) {
        CP_WAIT1();
        __syncthreads();

        uint32_t st = sb + rd * STAGEB;
        uint32_t aRow = st + (uint32_t)(wm * 64) * 128;
        uint32_t bRow = st + GMATB + (uint32_t)(wn * 64) * 128;

#pragma unroll
        for (int kb = 0; kb < 4; kb++) {
            uint32_t ah[4][4];
#pragma unroll
            for (int mt = 0; mt < 4; mt++)
                ldsm4(ah[mt], aRow + (uint32_t)(mt * 16 + arow) * 128
                              + (uint32_t)(((kb * 2 + asel) ^ axor) << 4));
#pragma unroll
            for (int p = 0; p < 4; p++) {
                uint32_t bh[4];
                ldsm4(bh, bRow + (uint32_t)(p * 16 + browl) * 128
                          + (uint32_t)(((kb * 2 + bsel) ^ bxor) << 4));
#pragma unroll
                for (int mt = 0; mt < 4; mt++) {
                    mma16816h(acc[mt][2 * p],     ah[mt], &bh[0]);
                    mma16816h(acc[mt][2 * p + 1], ah[mt], &bh[2]);
                }
            }
        }

        if (kt + 2 < nkt) {
            uint32_t st2 = sb + wr * STAGEB;
            int koff = (kt + 2) * 64;
#pragma unroll
            for (int mat = 0; mat < 2; mat++)
#pragma unroll
                for (int r8 = 0; r8 < 8; r8++)
                    cp16(st2 + mat * GMATB + wbase + r8 * 16 * 128,
                         gp[mat] + (size_t)(lr + r8 * 16) * K + koff + lc * 8);
        }
        CP_COMMIT();
        rd = (rd == 2) ? 0 : rd + 1;
        wr = (wr == 2) ? 0 : wr + 1;
    }

    int rA = m0 + wm * 64 + (lid >> 2);
    int cA = n0 + wn * 64 + 2 * (lid & 3);
#pragma unroll
    for (int mt = 0; mt < 4; mt++) {
        int r = rA + mt * 16;
#pragma unroll
        for (int nt = 0; nt < 8; nt++) {
            int c = cA + nt * 8;
            float b0 = bias[c], b1 = bias[c + 1];
            float2 w0 = { acc[mt][nt][0] + b0, acc[mt][nt][1] + b1 };
            float2 w1 = { acc[mt][nt][2] + b0, acc[mt][nt][3] + b1 };
            *(float2*)(Cf + (size_t)r * N + c)       = w0;
            *(float2*)(Cf + (size_t)(r + 8) * N + c) = w1;
        }
    }
}

// ---------------------------------------------------------------------------
// fp16 single-pass causal flash attention (unchanged round 14).
// ---------------------------------------------------------------------------
#define QMATB   16384
#define FMATB   8192
#define FSTAGE  (2 * FMATB)
#define FSMEM   (QMATB + 2 * FSTAGE)  // 49152
#define SCALE_L2E 0.18033688011112042f

__global__ __launch_bounds__(256, 2)
void flash_mma(const __half* __restrict__ qkv, __half* __restrict__ attf)
{
    extern __shared__ char smem[];
    uint32_t sb = smem_u32(smem);
    int t = threadIdx.x, wid = t >> 5, lid = t & 31;
    int bh = blockIdx.x;
    int b = bh >> 4, hh = bh & 15;
    int qt = (int)gridDim.y - 1 - blockIdx.y;
    int qbase = qt * 128;
    int tok0 = b * S_LEN;

    const uint32_t QH = sb;
    const uint32_t KV0 = sb + QMATB;

    const int qlrow  = t >> 1;
    const int qlcol0 = (t & 1) * 4;
    const int klrow  = t >> 2;
    const int klcol0 = (t & 3) * 2;
    const int klx = klrow & 7;

    {
        size_t rq = (size_t)(tok0 + qbase + qlrow) * E3 + hh * 64;
        int qx = qlrow & 7;
#pragma unroll
        for (int u = 0; u < 4; u++) {
            int ch = qlcol0 + u;
            cp16(QH + qlrow * 128 + ((ch ^ qx) << 4), qkv + rq + ch * 8);
        }
        size_t rk = (size_t)(tok0 + klrow) * E3 + 1024 + hh * 64;
#pragma unroll
        for (int u = 0; u < 2; u++) {
            int ch = klcol0 + u;
            uint32_t d = klrow * 128 + ((ch ^ klx) << 4);
            cp16(KV0 + d,         qkv + rk + ch * 8);
            cp16(KV0 + FMATB + d, qkv + rk + 1024 + ch * 8);
        }
    }
    CP_COMMIT();

    const int arow = lid & 15, asel = lid >> 4;
    const int qrow = wid * 16 + arow;
    const int qx = qrow & 7;
    const int browf = ((lid >> 4) & 1) * 8 + (lid & 7);
    const int bsel = (lid >> 3) & 1;
    const int vrowf = ((lid >> 3) & 1) * 8 + (lid & 7);
    const int vsel = (lid >> 4) & 1;

    uint32_t qh[4][4];
    float o[8][4];
#pragma unroll
    for (int n = 0; n < 8; n++)
#pragma unroll
        for (int v = 0; v < 4; v++) o[n][v] = 0.f;
    float m_lo = -CUDART_INF_F, m_hi = -CUDART_INF_F, l_lo = 0.f, l_hi = 0.f;

    const int rlo = lid >> 2;
    const int rloc = 16 * (wid & 3) + rlo;
    const int mycol0 = 2 * (lid & 3);
    const int kt_d = 2 * qt + (wid >> 2);
    const int ntiles = 2 * qt + 2;
    const uint32_t bones[2] = { 0x3C003C00u, 0x3C003C00u };

    for (int kt = 0; kt < ntiles; kt++) {
        if (kt + 1 < ntiles) {
            uint32_t st = KV0 + ((kt + 1) & 1) * FSTAGE;
            size_t rk = (size_t)(tok0 + (kt + 1) * 64 + klrow) * E3 + 1024 + hh * 64;
#pragma unroll
            for (int u = 0; u < 2; u++) {
                int ch = klcol0 + u;
                uint32_t d = klrow * 128 + ((ch ^ klx) << 4);
                cp16(st + d,         qkv + rk + ch * 8);
                cp16(st + FMATB + d, qkv + rk + 1024 + ch * 8);
            }
        }
        CP_COMMIT();
        CP_WAIT1();
        __syncthreads();

        if (kt == 0) {
#pragma unroll
            for (int ks = 0; ks < 4; ks++)
                ldsm4(qh[ks], QH + qrow * 128 + (((ks * 2 + asel) ^ qx) << 4));
        }

        if (kt <= kt_d) {
            uint32_t st = KV0 + (kt & 1) * FSTAGE;

            float s[8][4];
#pragma unroll
            for (int n = 0; n < 8; n++)
#pragma unroll
                for (int v = 0; v < 4; v++) s[n][v] = 0.f;

#pragma unroll
            for (int ks = 0; ks < 4; ks++) {
#pragma unroll
                for (int pp = 0; pp < 2; pp++) {
                    int p0 = pp * 2;
                    int rk0 = p0 * 16 + browf, rk1 = rk0 + 16;
                    uint32_t ka0 = st + rk0 * 128 + (((ks * 2 + bsel) ^ (rk0 & 7)) << 4);
                    uint32_t ka1 = st + rk1 * 128 + (((ks * 2 + bsel) ^ (rk1 & 7)) << 4);
                    uint32_t kh0[4], kh1[4];
                    ldsm4(kh0, ka0);
                    ldsm4(kh1, ka1);
                    mma16816h(s[2 * p0],     qh[ks], &kh0[0]);
                    mma16816h(s[2 * p0 + 1], qh[ks], &kh0[2]);
                    mma16816h(s[2 * p0 + 2], qh[ks], &kh1[0]);
                    mma16816h(s[2 * p0 + 3], qh[ks], &kh1[2]);
                }
            }

#pragma unroll
            for (int n = 0; n < 8; n++)
#pragma unroll
                for (int v = 0; v < 4; v++) s[n][v] *= SCALE_L2E;

            if (kt == kt_d) {
#pragma unroll
                for (int n = 0; n < 8; n++) {
                    int c0 = n * 8 + mycol0;
                    if (c0 > rloc)     s[n][0] = -CUDART_INF_F;
                    if (c0 + 1 > rloc) s[n][1] = -CUDART_INF_F;
                    if (c0 > rloc + 8)     s[n][2] = -CUDART_INF_F;
                    if (c0 + 1 > rloc + 8) s[n][3] = -CUDART_INF_F;
                }
            }

            float mt_lo = -CUDART_INF_F, mt_hi = -CUDART_INF_F;
#pragma unroll
            for (int n = 0; n < 8; n++) {
                mt_lo = fmaxf(mt_lo, fmaxf(s[n][0], s[n][1]));
                mt_hi = fmaxf(mt_hi, fmaxf(s[n][2], s[n][3]));
            }
            mt_lo = fmaxf(mt_lo, __shfl_xor_sync(0xffffffffu, mt_lo, 1));
            mt_lo = fmaxf(mt_lo, __shfl_xor_sync(0xffffffffu, mt_lo, 2));
            mt_hi = fmaxf(mt_hi, __shfl_xor_sync(0xffffffffu, mt_hi, 1));
            mt_hi = fmaxf(mt_hi, __shfl_xor_sync(0xffffffffu, mt_hi, 2));

            float mn_lo = fmaxf(m_lo, mt_lo), mn_hi = fmaxf(m_hi, mt_hi);
            float a_lo = exp2f(m_lo - mn_lo), a_hi = exp2f(m_hi - mn_hi);
            m_lo = mn_lo; m_hi = mn_hi;

            uint32_t plo[8], phi[8];
#pragma unroll
            for (int n = 0; n < 8; n++) {
                plo[n] = ex2_h2(pack2h(s[n][0] - mn_lo, s[n][1] - mn_lo));
                phi[n] = ex2_h2(pack2h(s[n][2] - mn_hi, s[n][3] - mn_hi));
            }

            float accl[4] = {0.f, 0.f, 0.f, 0.f};
#pragma unroll
            for (int ks = 0; ks < 4; ks++) {
                uint32_t pa[4] = { plo[2 * ks], phi[2 * ks],
                                   plo[2 * ks + 1], phi[2 * ks + 1] };
                mma16816h(accl, pa, bones);
            }
            l_lo = a_lo * l_lo + accl[0];
            l_hi = a_hi * l_hi + accl[2];
#pragma unroll
            for (int n = 0; n < 8; n++) {
                o[n][0] *= a_lo; o[n][1] *= a_lo;
                o[n][2] *= a_hi; o[n][3] *= a_hi;
            }

            uint32_t vbase = st + FMATB;
#pragma unroll
            for (int ks = 0; ks < 4; ks++) {
                uint32_t pa[4] = { plo[2 * ks], phi[2 * ks],
                                   plo[2 * ks + 1], phi[2 * ks + 1] };
                int rv = ks * 16 + vrowf;
                int vx = rv & 7;
#pragma unroll
                for (int pp = 0; pp < 2; pp++) {
                    int p0 = pp * 2;
                    uint32_t va0 = vbase + rv * 128 + (((p0 * 2 + vsel) ^ vx) << 4);
                    uint32_t va1 = vbase + rv * 128 + ((((p0 + 1) * 2 + vsel) ^ vx) << 4);
                    uint32_t vh0[4], vh1[4];
                    ldsm4t(vh0, va0);
                    ldsm4t(vh1, va1);
                    mma16816h(o[2 * p0],     pa, &vh0[0]);
                    mma16816h(o[2 * p0 + 1], pa, &vh0[2]);
                    mma16816h(o[2 * p0 + 2], pa, &vh1[0]);
                    mma16816h(o[2 * p0 + 3], pa, &vh1[2]);
                }
            }
        }
        __syncthreads();
    }

    float inv_lo = 1.f / l_lo, inv_hi = 1.f / l_hi;
    int tok_lo = tok0 + qbase + wid * 16 + rlo;
    int tok_hi = tok_lo + 8;
#pragma unroll
    for (int n = 0; n < 8; n++) {
        int c = hh * 64 + n * 8 + mycol0;
        *(uint32_t*)(attf + (size_t)tok_lo * N_EMBD + c) =
            pack2h(o[n][0] * inv_lo, o[n][1] * inv_lo);
        *(uint32_t*)(attf + (size_t)tok_hi * N_EMBD + c) =
            pack2h(o[n][2] * inv_hi, o[n][3] * inv_hi);
    }
}

// ---------------------------------------------------------------------------
extern "C" void kernel_launch(void* const* d_in, const int* in_sizes, int n_in,
                              void* d_out, int out_size)
{
    const float* x      = (const float*)d_in[0];
    const float* W_attn = (const float*)d_in[1];
    const float* b_attn = (const float*)d_in[2];
    const float* W_proj = (const float*)d_in[3];
    const float* b_proj = (const float*)d_in[4];
    float* out = (float*)d_out;

    __half *xf, *attf, *qkv, *wa, *wp;
    cudaGetSymbolAddress((void**)&xf, g_xf);
    cudaGetSymbolAddress((void**)&attf, g_attf);
    cudaGetSymbolAddress((void**)&qkv, g_qkv);
    cudaGetSymbolAddress((void**)&wa, g_wa);
    cudaGetSymbolAddress((void**)&wp, g_wp);

    cudaFuncSetAttribute(gemm_qkv,
                         cudaFuncAttributeMaxDynamicSharedMemorySize, QSMEM);
    cudaFuncSetAttribute(gemm_proj,
                         cudaFuncAttributeMaxDynamicSharedMemorySize, GSMEM);
    cudaFuncSetAttribute(flash_mma,
                         cudaFuncAttributeMaxDynamicSharedMemorySize, FSMEM);

    cvt_f16<<<(M_ROWS * N_EMBD / 4 + 255) / 256, 256>>>(x, xf, M_ROWS * N_EMBD / 4);
    cvt_t_16<<<dim3(E3 / 32, N_EMBD / 32), dim3(32, 8)>>>(W_attn, wa, N_EMBD, E3);
    cvt_t_16<<<dim3(N_EMBD / 32, N_EMBD / 32), dim3(32, 8)>>>(W_proj, wp, N_EMBD, N_EMBD);

    // 1) QKV projection: 128x96 tiles, 3 CTAs/SM
    gemm_qkv<<<dim3(E3 / 96, M_ROWS / 128), 128, QSMEM>>>(
        xf, wa, b_attn, qkv, M_ROWS, E3, N_EMBD);

    // 2) fp16 single-pass causal flash attention
    flash_mma<<<dim3(2 * N_HEADS, S_LEN / 128), 256, FSMEM>>>(qkv, attf);

    // 3) output projection -> fp32
    gemm_proj<<<dim3(N_EMBD / 128, M_ROWS / 128), 128, GSMEM>>>(
        attf, wp, b_proj, out, M_ROWS, N_EMBD, N_EMBD);
}

// round 16
// speedup vs baseline: 1.1244x; 1.0877x over previous
#include <cuda_runtime.h>
#include <cuda_bf16.h>
#include <cuda_fp16.h>
#include <math_constants.h>
#include <cstdint>

// ---------------------------------------------------------------------------
// MultiHeadAttention, B=2,S=2048,H=16,D=64,E=1024. All-fp16 HMMA pipeline,
// single-pass everywhere.
//   0) prep_all: x->fp16, W_attn^T, W_proj^T in ONE kernel (round 16)
//   1) qkv(fp16) = x @ Wattn + b   [128x96 tiles, BK=32, 3 CTAs/SM]
//   2) att(fp16) = flash(qkv)      [S=Qh*Kh, O=Ph*Vh; 3-stage KV pipeline]
//   3) out(fp32) = att @ Wproj + b [128x128, BK=64, 2 CTAs/SM]
// ---------------------------------------------------------------------------

#define S_LEN   2048
#define N_EMBD  1024
#define E3      3072
#define N_HEADS 16
#define M_ROWS  4096

__device__ __half g_xf[(size_t)M_ROWS * N_EMBD];
__device__ __half g_attf[(size_t)M_ROWS * N_EMBD];
__device__ __half g_qkv[(size_t)M_ROWS * E3];
__device__ __half g_wa[(size_t)E3 * N_EMBD];     // W_attn^T fp16
__device__ __half g_wp[(size_t)N_EMBD * N_EMBD]; // W_proj^T fp16

// ------------------------- helpers ------------------------------------------
__device__ __forceinline__ uint32_t smem_u32(const void* p) {
    uint32_t a;
    asm("{ .reg .u64 t; cvta.to.shared.u64 t, %1; cvt.u32.u64 %0, t; }"
        : "=r"(a) : "l"(p));
    return a;
}
__device__ __forceinline__ void cp16(uint32_t dst, const void* src) {
    asm volatile("cp.async.cg.shared.global [%0], [%1], 16;" :: "r"(dst), "l"(src));
}
#define CP_COMMIT() asm volatile("cp.async.commit_group;" ::: "memory")
#define CP_WAIT1()  asm volatile("cp.async.wait_group 1;"  ::: "memory")

__device__ __forceinline__ void ldsm4(uint32_t* r, uint32_t addr) {
    asm volatile("ldmatrix.sync.aligned.m8n8.x4.shared.b16 {%0,%1,%2,%3}, [%4];"
                 : "=r"(r[0]), "=r"(r[1]), "=r"(r[2]), "=r"(r[3]) : "r"(addr));
}
__device__ __forceinline__ void ldsm4t(uint32_t* r, uint32_t addr) {
    asm volatile("ldmatrix.sync.aligned.m8n8.x4.trans.shared.b16 {%0,%1,%2,%3}, [%4];"
                 : "=r"(r[0]), "=r"(r[1]), "=r"(r[2]), "=r"(r[3]) : "r"(addr));
}
__device__ __forceinline__ void mma16816h(float* d, const uint32_t* a, const uint32_t* b) {
    asm volatile(
        "mma.sync.aligned.m16n8k16.row.col.f32.f16.f16.f32 "
        "{%0,%1,%2,%3}, {%4,%5,%6,%7}, {%8,%9}, {%0,%1,%2,%3};"
        : "+f"(d[0]), "+f"(d[1]), "+f"(d[2]), "+f"(d[3])
        : "r"(a[0]), "r"(a[1]), "r"(a[2]), "r"(a[3]), "r"(b[0]), "r"(b[1]));
}
__device__ __forceinline__ uint32_t pack2h(float a, float b) {
    uint32_t r;
    asm("cvt.rn.f16x2.f32 %0, %1, %2;" : "=r"(r) : "f"(b), "f"(a));
    return r;
}
__device__ __forceinline__ uint32_t ex2_h2(uint32_t h2) {
    asm("ex2.approx.f16x2 %0, %0;" : "+r"(h2));
    return h2;
}

// ---------------------------------------------------------------------------
// Fused operand prep: one launch covers x-cast + both weight transposes.
// Blocks [0,4096): x fp32->fp16 (256 float4 each)
// Blocks [4096,7168): W_attn^T tiles (96 x 32 grid of 32x32 tiles)
// Blocks [7168,8192): W_proj^T tiles (32 x 32)
// ---------------------------------------------------------------------------
__device__ __forceinline__ void tpose_tile(const float* __restrict__ W,
                                           __half* __restrict__ T,
                                           int K, int N, int bx, int by, int t,
                                           float (*tile)[33])
{
    int tx = t & 31, ty = t >> 5;
    int k0 = by * 32, n0 = bx * 32;
#pragma unroll
    for (int i = ty; i < 32; i += 8)
        tile[i][tx] = W[(size_t)(k0 + i) * N + n0 + tx];
    __syncthreads();
#pragma unroll
    for (int i = ty; i < 32; i += 8)
        T[(size_t)(n0 + i) * K + k0 + tx] = __float2half_rn(tile[tx][i]);
}

__global__ void prep_all(const float* __restrict__ x, __half* __restrict__ xf,
                         const float* __restrict__ Wa, __half* __restrict__ wa,
                         const float* __restrict__ Wp, __half* __restrict__ wp)
{
    __shared__ float tile[32][33];
    int blk = blockIdx.x, t = threadIdx.x;
    if (blk < 4096) {
        int i = blk * 256 + t;
        float4 v = ((const float4*)x)[i];
        uint2 o = { pack2h(v.x, v.y), pack2h(v.z, v.w) };
        ((uint2*)xf)[i] = o;
    } else if (blk < 7168) {
        int bb = blk - 4096;
        tpose_tile(Wa, wa, N_EMBD, E3, bb % 96, bb / 96, t, tile);
    } else {
        int bb = blk - 7168;
        tpose_tile(Wp, wp, N_EMBD, N_EMBD, bb % 32, bb / 32, t, tile);
    }
}

// ---------------------------------------------------------------------------
// QKV GEMM (unchanged round 15): 128x96 CTA, BK=32, 4 warps 64x48,
// 3 stages x 14KB, 3 CTAs/SM, 128 threads, fp16 out.
// ---------------------------------------------------------------------------
#define QAMATB 8192
#define QBMATB 6144
#define QSTAGE (QAMATB + QBMATB)
#define QSMEM  (3 * QSTAGE)      // 43008

__global__ __launch_bounds__(128, 3)
void gemm_qkv(const __half* __restrict__ A, const __half* __restrict__ B,
              const float* __restrict__ bias, __half* __restrict__ C,
              int M, int N, int K)
{
    extern __shared__ char smem[];
    uint32_t sb = smem_u32(smem);
    int t = threadIdx.x, wid = t >> 5, lid = t & 31;
    int m0 = blockIdx.y * 128, n0 = blockIdx.x * 96;
    int wm = wid & 1, wn = wid >> 1;

    const __half* gA = A + (size_t)m0 * K;
    const __half* gB = B + (size_t)n0 * K;

    const int lc = t & 3;
    const int lr = t >> 2;
    const uint32_t wofs = (uint32_t)((lc ^ ((lr >> 1) & 3)) << 4) + lr * 64;

    float acc[4][6][4];
#pragma unroll
    for (int i = 0; i < 4; i++)
#pragma unroll
        for (int j = 0; j < 6; j++)
#pragma unroll
            for (int v = 0; v < 4; v++) acc[i][j][v] = 0.f;

    int nkt = K / 32;

#pragma unroll
    for (int s = 0; s < 2; s++) {
        uint32_t st = sb + s * QSTAGE;
        int koff = s * 32;
#pragma unroll
        for (int k4 = 0; k4 < 4; k4++)
            cp16(st + wofs + k4 * 32 * 64,
                 gA + (size_t)(lr + k4 * 32) * K + koff + lc * 8);
#pragma unroll
        for (int k3 = 0; k3 < 3; k3++)
            cp16(st + QAMATB + wofs + k3 * 32 * 64,
                 gB + (size_t)(lr + k3 * 32) * K + koff + lc * 8);
        CP_COMMIT();
    }

    const int arow = lid & 15, asel = lid >> 4;
    const int axor = (arow >> 1) & 3;
    const int browl = ((lid >> 4) & 1) * 8 + (lid & 7);
    const int bsel = (lid >> 3) & 1;
    const int bxor = (browl >> 1) & 3;

    int rd = 0, wr = 2;
    for (int kt = 0; kt < nkt; kt++) {
        CP_WAIT1();
        __syncthreads();

        uint32_t st = sb + rd * QSTAGE;

#pragma unroll
        for (int kb = 0; kb < 2; kb++) {
            uint32_t ah[4][4];
#pragma unroll
            for (int mt = 0; mt < 4; mt++)
                ldsm4(ah[mt], st + (uint32_t)(wm * 64 + mt * 16 + arow) * 64
                              + (uint32_t)(((kb * 2 + asel) ^ axor) << 4));
#pragma unroll
            for (int p = 0; p < 3; p++) {
                uint32_t bh[4];
                ldsm4(bh, st + QAMATB
                          + (uint32_t)(wn * 48 + p * 16 + browl) * 64
                          + (uint32_t)(((kb * 2 + bsel) ^ bxor) << 4));
#pragma unroll
                for (int mt = 0; mt < 4; mt++) {
                    mma16816h(acc[mt][2 * p],     ah[mt], &bh[0]);
                    mma16816h(acc[mt][2 * p + 1], ah[mt], &bh[2]);
                }
            }
        }

        if (kt + 2 < nkt) {
            uint32_t st2 = sb + wr * QSTAGE;
            int koff = (kt + 2) * 32;
#pragma unroll
            for (int k4 = 0; k4 < 4; k4++)
                cp16(st2 + wofs + k4 * 32 * 64,
                     gA + (size_t)(lr + k4 * 32) * K + koff + lc * 8);
#pragma unroll
            for (int k3 = 0; k3 < 3; k3++)
                cp16(st2 + QAMATB + wofs + k3 * 32 * 64,
                     gB + (size_t)(lr + k3 * 32) * K + koff + lc * 8);
        }
        CP_COMMIT();
        rd = (rd == 2) ? 0 : rd + 1;
        wr = (wr == 2) ? 0 : wr + 1;
    }

    int rA = m0 + wm * 64 + (lid >> 2);
    int cA = n0 + wn * 48 + 2 * (lid & 3);
#pragma unroll
    for (int mt = 0; mt < 4; mt++) {
        int r = rA + mt * 16;
#pragma unroll
        for (int nt = 0; nt < 6; nt++) {
            int c = cA + nt * 8;
            float b0 = bias[c], b1 = bias[c + 1];
            *(uint32_t*)(C + (size_t)r * N + c) =
                pack2h(acc[mt][nt][0] + b0, acc[mt][nt][1] + b1);
            *(uint32_t*)(C + (size_t)(r + 8) * N + c) =
                pack2h(acc[mt][nt][2] + b0, acc[mt][nt][3] + b1);
        }
    }
}

// ---------------------------------------------------------------------------
// Proj GEMM (unchanged): 128x128, BK=64, 2 CTAs/SM, fp32 out.
// ---------------------------------------------------------------------------
#define GMATB  16384
#define STAGEB (2 * GMATB)
#define GSMEM  (3 * STAGEB)      // 98304

__global__ __launch_bounds__(128, 2)
void gemm_proj(const __half* __restrict__ A, const __half* __restrict__ B,
               const float* __restrict__ bias, float* __restrict__ Cf,
               int M, int N, int K)
{
    extern __shared__ char smem[];
    uint32_t sb = smem_u32(smem);
    int t = threadIdx.x, wid = t >> 5, lid = t & 31;
    int m0 = blockIdx.y * 128, n0 = blockIdx.x * 128;
    int wm = wid & 1, wn = wid >> 1;

    const __half* gp[2] = { A + (size_t)m0 * K, B + (size_t)n0 * K };

    const int lc = t & 7;
    const int lr = t >> 3;
    const uint32_t wbase = (uint32_t)((lc ^ (lr & 7)) << 4) + lr * 128;

    float acc[4][8][4];
#pragma unroll
    for (int i = 0; i < 4; i++)
#pragma unroll
        for (int j = 0; j < 8; j++)
#pragma unroll
            for (int v = 0; v < 4; v++) acc[i][j][v] = 0.f;

    int nkt = K / 64;

#pragma unroll
    for (int s = 0; s < 2; s++) {
        uint32_t st = sb + s * STAGEB;
        int koff = s * 64;
#pragma unroll
        for (int mat = 0; mat < 2; mat++)
#pragma unroll
            for (int r8 = 0; r8 < 8; r8++)
                cp16(st + mat * GMATB + wbase + r8 * 16 * 128,
                     gp[mat] + (size_t)(lr + r8 * 16) * K + koff + lc * 8);
        CP_COMMIT();
    }

    const int arow = lid & 15, asel = lid >> 4;
    const int axor = arow & 7;
    const int browl = ((lid >> 4) & 1) * 8 + (lid & 7);
    const int bsel = (lid >> 3) & 1;
    const int bxor = browl & 7;

    int rd = 0, wr = 2;
    for (int kt = 0; kt < nkt; kt++) {
        CP_WAIT1();
        __syncthreads();

        uint32_t st = sb + rd * STAGEB;
        uint32_t aRow = st + (uint32_t)(wm * 64) * 128;
        uint32_t bRow = st + GMATB + (uint32_t)(wn * 64) * 128;

#pragma unroll
        for (int kb = 0; kb < 4; kb++) {
            uint32_t ah[4][4];
#pragma unroll
            for (int mt = 0; mt < 4; mt++)
                ldsm4(ah[mt], aRow + (uint32_t)(mt * 16 + arow) * 128
                              + (uint32_t)(((kb * 2 + asel) ^ axor) << 4));
#pragma unroll
            for (int p = 0; p < 4; p++) {
                uint32_t bh[4];
                ldsm4(bh, bRow + (uint32_t)(p * 16 + browl) * 128
                          + (uint32_t)(((kb * 2 + bsel) ^ bxor) << 4));
#pragma unroll
                for (int mt = 0; mt < 4; mt++) {
                    mma16816h(acc[mt][2 * p],     ah[mt], &bh[0]);
                    mma16816h(acc[mt][2 * p + 1], ah[mt], &bh[2]);
                }
            }
        }

        if (kt + 2 < nkt) {
            uint32_t st2 = sb + wr * STAGEB;
            int koff = (kt + 2) * 64;
#pragma unroll
            for (int mat = 0; mat < 2; mat++)
#pragma unroll
                for (int r8 = 0; r8 < 8; r8++)
                    cp16(st2 + mat * GMATB + wbase + r8 * 16 * 128,
                         gp[mat] + (size_t)(lr + r8 * 16) * K + koff + lc * 8);
        }
        CP_COMMIT();
        rd = (rd == 2) ? 0 : rd + 1;
        wr = (wr == 2) ? 0 : wr + 1;
    }

    int rA = m0 + wm * 64 + (lid >> 2);
    int cA = n0 + wn * 64 + 2 * (lid & 3);
#pragma unroll
    for (int mt = 0; mt < 4; mt++) {
        int r = rA + mt * 16;
#pragma unroll
        for (int nt = 0; nt < 8; nt++) {
            int c = cA + nt * 8;
            float b0 = bias[c], b1 = bias[c + 1];
            float2 w0 = { acc[mt][nt][0] + b0, acc[mt][nt][1] + b1 };
            float2 w1 = { acc[mt][nt][2] + b0, acc[mt][nt][3] + b1 };
            *(float2*)(Cf + (size_t)r * N + c)       = w0;
            *(float2*)(Cf + (size_t)(r + 8) * N + c) = w1;
        }
    }
}

// ---------------------------------------------------------------------------
// fp16 single-pass causal flash attention, 3-stage KV pipeline with
// post-compute issue (GEMM-style), 1 barrier/tile.
// SMEM: Q 16KB + 3 KV stages x 16KB = 64KB -> 2 CTAs/SM.
// ---------------------------------------------------------------------------
#define QMATB   16384
#define FMATB   8192
#define FSTAGE  (2 * FMATB)      // 16384 (K | V)
#define FSMEM   (QMATB + 3 * FSTAGE)  // 65536
#define SCALE_L2E 0.18033688011112042f

__global__ __launch_bounds__(256, 2)
void flash_mma(const __half* __restrict__ qkv, __half* __restrict__ attf)
{
    extern __shared__ char smem[];
    uint32_t sb = smem_u32(smem);
    int t = threadIdx.x, wid = t >> 5, lid = t & 31;
    int bh = blockIdx.x;
    int b = bh >> 4, hh = bh & 15;
    int qt = (int)gridDim.y - 1 - blockIdx.y;
    int qbase = qt * 128;
    int tok0 = b * S_LEN;

    const uint32_t QH = sb;
    const uint32_t KV0 = sb + QMATB;

    const int qlrow  = t >> 1;
    const int qlcol0 = (t & 1) * 4;
    const int klrow  = t >> 2;
    const int klcol0 = (t & 3) * 2;
    const int klx = klrow & 7;

    const int ntiles = 2 * qt + 2;

    // prologue: Q + KV stage 0 (group 0), KV stage 1 (group 1)
    {
        size_t rq = (size_t)(tok0 + qbase + qlrow) * E3 + hh * 64;
        int qx = qlrow & 7;
#pragma unroll
        for (int u = 0; u < 4; u++) {
            int ch = qlcol0 + u;
            cp16(QH + qlrow * 128 + ((ch ^ qx) << 4), qkv + rq + ch * 8);
        }
        size_t rk = (size_t)(tok0 + klrow) * E3 + 1024 + hh * 64;
#pragma unroll
        for (int u = 0; u < 2; u++) {
            int ch = klcol0 + u;
            uint32_t d = klrow * 128 + ((ch ^ klx) << 4);
            cp16(KV0 + d,         qkv + rk + ch * 8);
            cp16(KV0 + FMATB + d, qkv + rk + 1024 + ch * 8);
        }
    }
    CP_COMMIT();
    if (1 < ntiles) {
        uint32_t st = KV0 + FSTAGE;
        size_t rk = (size_t)(tok0 + 64 + klrow) * E3 + 1024 + hh * 64;
#pragma unroll
        for (int u = 0; u < 2; u++) {
            int ch = klcol0 + u;
            uint32_t d = klrow * 128 + ((ch ^ klx) << 4);
            cp16(st + d,         qkv + rk + ch * 8);
            cp16(st + FMATB + d, qkv + rk + 1024 + ch * 8);
        }
    }
    CP_COMMIT();

    const int arow = lid & 15, asel = lid >> 4;
    const int qrow = wid * 16 + arow;
    const int qx = qrow & 7;
    const int browf = ((lid >> 4) & 1) * 8 + (lid & 7);
    const int bsel = (lid >> 3) & 1;
    const int vrowf = ((lid >> 3) & 1) * 8 + (lid & 7);
    const int vsel = (lid >> 4) & 1;

    uint32_t qh[4][4];
    float o[8][4];
#pragma unroll
    for (int n = 0; n < 8; n++)
#pragma unroll
        for (int v = 0; v < 4; v++) o[n][v] = 0.f;
    float m_lo = -CUDART_INF_F, m_hi = -CUDART_INF_F, l_lo = 0.f, l_hi = 0.f;

    const int rlo = lid >> 2;
    const int rloc = 16 * (wid & 3) + rlo;
    const int mycol0 = 2 * (lid & 3);
    const int kt_d = 2 * qt + (wid >> 2);
    const uint32_t bones[2] = { 0x3C003C00u, 0x3C003C00u };

    int rd = 0, wr = 2;
    for (int kt = 0; kt < ntiles; kt++) {
        CP_WAIT1();
        __syncthreads();

        if (kt == 0) {
#pragma unroll
            for (int ks = 0; ks < 4; ks++)
                ldsm4(qh[ks], QH + qrow * 128 + (((ks * 2 + asel) ^ qx) << 4));
        }

        if (kt <= kt_d) {
            uint32_t st = KV0 + rd * FSTAGE;

            // ---- S = Qh * Kh ----
            float s[8][4];
#pragma unroll
            for (int n = 0; n < 8; n++)
#pragma unroll
                for (int v = 0; v < 4; v++) s[n][v] = 0.f;

#pragma unroll
            for (int ks = 0; ks < 4; ks++) {
#pragma unroll
                for (int pp = 0; pp < 2; pp++) {
                    int p0 = pp * 2;
                    int rk0 = p0 * 16 + browf, rk1 = rk0 + 16;
                    uint32_t ka0 = st + rk0 * 128 + (((ks * 2 + bsel) ^ (rk0 & 7)) << 4);
                    uint32_t ka1 = st + rk1 * 128 + (((ks * 2 + bsel) ^ (rk1 & 7)) << 4);
                    uint32_t kh0[4], kh1[4];
                    ldsm4(kh0, ka0);
                    ldsm4(kh1, ka1);
                    mma16816h(s[2 * p0],     qh[ks], &kh0[0]);
                    mma16816h(s[2 * p0 + 1], qh[ks], &kh0[2]);
                    mma16816h(s[2 * p0 + 2], qh[ks], &kh1[0]);
                    mma16816h(s[2 * p0 + 3], qh[ks], &kh1[2]);
                }
            }

#pragma unroll
            for (int n = 0; n < 8; n++)
#pragma unroll
                for (int v = 0; v < 4; v++) s[n][v] *= SCALE_L2E;

            if (kt == kt_d) {
#pragma unroll
                for (int n = 0; n < 8; n++) {
                    int c0 = n * 8 + mycol0;
                    if (c0 > rloc)     s[n][0] = -CUDART_INF_F;
                    if (c0 + 1 > rloc) s[n][1] = -CUDART_INF_F;
                    if (c0 > rloc + 8)     s[n][2] = -CUDART_INF_F;
                    if (c0 + 1 > rloc + 8) s[n][3] = -CUDART_INF_F;
                }
            }

            // ---- row max + rescale ----
            float mt_lo = -CUDART_INF_F, mt_hi = -CUDART_INF_F;
#pragma unroll
            for (int n = 0; n < 8; n++) {
                mt_lo = fmaxf(mt_lo, fmaxf(s[n][0], s[n][1]));
                mt_hi = fmaxf(mt_hi, fmaxf(s[n][2], s[n][3]));
            }
            mt_lo = fmaxf(mt_lo, __shfl_xor_sync(0xffffffffu, mt_lo, 1));
            mt_lo = fmaxf(mt_lo, __shfl_xor_sync(0xffffffffu, mt_lo, 2));
            mt_hi = fmaxf(mt_hi, __shfl_xor_sync(0xffffffffu, mt_hi, 1));
            mt_hi = fmaxf(mt_hi, __shfl_xor_sync(0xffffffffu, mt_hi, 2));

            float mn_lo = fmaxf(m_lo, mt_lo), mn_hi = fmaxf(m_hi, mt_hi);
            float a_lo = exp2f(m_lo - mn_lo), a_hi = exp2f(m_hi - mn_hi);
            m_lo = mn_lo; m_hi = mn_hi;

            // ---- P = exp2(s - m) packed fp16 ----
            uint32_t plo[8], phi[8];
#pragma unroll
            for (int n = 0; n < 8; n++) {
                plo[n] = ex2_h2(pack2h(s[n][0] - mn_lo, s[n][1] - mn_lo));
                phi[n] = ex2_h2(pack2h(s[n][2] - mn_hi, s[n][3] - mn_hi));
            }

            // ---- row sums via MMA vs all-ones ----
            float accl[4] = {0.f, 0.f, 0.f, 0.f};
#pragma unroll
            for (int ks = 0; ks < 4; ks++) {
                uint32_t pa[4] = { plo[2 * ks], phi[2 * ks],
                                   plo[2 * ks + 1], phi[2 * ks + 1] };
                mma16816h(accl, pa, bones);
            }
            l_lo = a_lo * l_lo + accl[0];
            l_hi = a_hi * l_hi + accl[2];
#pragma unroll
            for (int n = 0; n < 8; n++) {
                o[n][0] *= a_lo; o[n][1] *= a_lo;
                o[n][2] *= a_hi; o[n][3] *= a_hi;
            }

            // ---- O += Ph * Vh ----
            uint32_t vbase = st + FMATB;
#pragma unroll
            for (int ks = 0; ks < 4; ks++) {
                uint32_t pa[4] = { plo[2 * ks], phi[2 * ks],
                                   plo[2 * ks + 1], phi[2 * ks + 1] };
                int rv = ks * 16 + vrowf;
                int vx = rv & 7;
#pragma unroll
                for (int pp = 0; pp < 2; pp++) {
                    int p0 = pp * 2;
                    uint32_t va0 = vbase + rv * 128 + (((p0 * 2 + vsel) ^ vx) << 4);
                    uint32_t va1 = vbase + rv * 128 + ((((p0 + 1) * 2 + vsel) ^ vx) << 4);
                    uint32_t vh0[4], vh1[4];
                    ldsm4t(vh0, va0);
                    ldsm4t(vh1, va1);
                    mma16816h(o[2 * p0],     pa, &vh0[0]);
                    mma16816h(o[2 * p0 + 1], pa, &vh0[2]);
                    mma16816h(o[2 * p0 + 2], pa, &vh1[0]);
                    mma16816h(o[2 * p0 + 3], pa, &vh1[2]);
                }
            }
        }

        // issue KV for tile kt+2 into stage wr == (kt-1)%3 (drained: all
        // threads passed this iteration's barrier after reading it in kt-1)
        if (kt + 2 < ntiles) {
            uint32_t st2 = KV0 + wr * FSTAGE;
            size_t rk = (size_t)(tok0 + (kt + 2) * 64 + klrow) * E3 + 1024 + hh * 64;
#pragma unroll
            for (int u = 0; u < 2; u++) {
                int ch = klcol0 + u;
                uint32_t d = klrow * 128 + ((ch ^ klx) << 4);
                cp16(st2 + d,         qkv + rk + ch * 8);
                cp16(st2 + FMATB + d, qkv + rk + 1024 + ch * 8);
            }
        }
        CP_COMMIT();
        rd = (rd == 2) ? 0 : rd + 1;
        wr = (wr == 2) ? 0 : wr + 1;
    }

    // ---- epilogue ----
    float inv_lo = 1.f / l_lo, inv_hi = 1.f / l_hi;
    int tok_lo = tok0 + qbase + wid * 16 + rlo;
    int tok_hi = tok_lo + 8;
#pragma unroll
    for (int n = 0; n < 8; n++) {
        int c = hh * 64 + n * 8 + mycol0;
        *(uint32_t*)(attf + (size_t)tok_lo * N_EMBD + c) =
            pack2h(o[n][0] * inv_lo, o[n][1] * inv_lo);
        *(uint32_t*)(attf + (size_t)tok_hi * N_EMBD + c) =
            pack2h(o[n][2] * inv_hi, o[n][3] * inv_hi);
    }
}

// ---------------------------------------------------------------------------
extern "C" void kernel_launch(void* const* d_in, const int* in_sizes, int n_in,
                              void* d_out, int out_size)
{
    const float* x      = (const float*)d_in[0];
    const float* W_attn = (const float*)d_in[1];
    const float* b_attn = (const float*)d_in[2];
    const float* W_proj = (const float*)d_in[3];
    const float* b_proj = (const float*)d_in[4];
    float* out = (float*)d_out;

    __half *xf, *attf, *qkv, *wa, *wp;
    cudaGetSymbolAddress((void**)&xf, g_xf);
    cudaGetSymbolAddress((void**)&attf, g_attf);
    cudaGetSymbolAddress((void**)&qkv, g_qkv);
    cudaGetSymbolAddress((void**)&wa, g_wa);
    cudaGetSymbolAddress((void**)&wp, g_wp);

    cudaFuncSetAttribute(gemm_qkv,
                         cudaFuncAttributeMaxDynamicSharedMemorySize, QSMEM);
    cudaFuncSetAttribute(gemm_proj,
                         cudaFuncAttributeMaxDynamicSharedMemorySize, GSMEM);
    cudaFuncSetAttribute(flash_mma,
                         cudaFuncAttributeMaxDynamicSharedMemorySize, FSMEM);

    // 0) fused operand prep (one launch)
    prep_all<<<8192, 256>>>(x, xf, W_attn, wa, W_proj, wp);

    // 1) QKV projection
    gemm_qkv<<<dim3(E3 / 96, M_ROWS / 128), 128, QSMEM>>>(
        xf, wa, b_attn, qkv, M_ROWS, E3, N_EMBD);

    // 2) flash attention
    flash_mma<<<dim3(2 * N_HEADS, S_LEN / 128), 256, FSMEM>>>(qkv, attf);

    // 3) output projection
    gemm_proj<<<dim3(N_EMBD / 128, M_ROWS / 128), 128, GSMEM>>>(
        attf, wp, b_proj, out, M_ROWS, N_EMBD, N_EMBD);
}